// round 8
// baseline (speedup 1.0000x reference)
#include <cuda_runtime.h>
#include <math.h>

#define DD 31
#define DIMV 32
#define TSTRIDE 36   // floats per s_T row (32 data + 4 pad; 144B keeps rows 16B-aligned)
#define MARGIN 0.85f

__device__ __forceinline__ float gelu_exact(float x) {
    return 0.5f * x * (1.0f + erff(x * 0.70710678118654752440f));
}

__device__ __forceinline__ float warp_sum(float v) {
#pragma unroll
    for (int o = 16; o; o >>= 1) v += __shfl_xor_sync(0xffffffffu, v, o);
    return v;
}

__global__ __launch_bounds__(256, 2)
void hypernet_kernel(const int* __restrict__ g_u, const int* __restrict__ g_r,
                     const int* __restrict__ g_v, const float* __restrict__ emb,
                     const float* __restrict__ bias_head, const float* __restrict__ bias_tail,
                     const float* __restrict__ head_rot_w, const float* __restrict__ head_boost_w,
                     const float* __restrict__ tail_rot_w, const float* __restrict__ tail_boost_w,
                     float* __restrict__ out, int N) {
    __shared__ __align__(16) float s_wt[DD][DIMV];      // gelu'd tail Householder rows; col31 = 0
    __shared__ __align__(16) float s_wh[DD][DIMV];      // gelu'd head rows; [i][31] = 2/n2
    __shared__ __align__(16) float s_T[DIMV][TSTRIDE];  // fused rot+boost matrix, row = input dim
    __shared__ __align__(16) float s_th[DIMV];          // transformed head vector (time at [0])
    __shared__ __align__(16) float s_ro[DIMV];          // tail rapidity (31 vals) + pad 0
    __shared__ float s_beta[DD];                        // -2/n2 per tail reflection
    __shared__ float s_par[4];                          // zeta_t, kappa_t, tanh(bias_head[u])

    const int b    = blockIdx.x;
    const int tid  = threadIdx.x;
    const int lane = tid & 31;
    const int wid  = tid >> 5;
    const int rb   = g_r[b];

    // ---------------- Phase A: gelu both rotation tables into shared ----------------
    const float* tw = tail_rot_w + (long)rb * (DD * DD);
    const float* hw = head_rot_w + (long)rb * (DD * DD);
    for (int k = tid; k < DD * DIMV; k += 256) {
        int i = k >> 5, j = k & 31;
        s_wt[i][j] = (j < DD) ? gelu_exact(tw[i * DD + j]) : 0.f;
        s_wh[i][j] = (j < DD) ? gelu_exact(hw[i * DD + j]) : 0.f;
    }
    __syncthreads();

    // ---------------- Phase A2: boost params + row norms + head bias ----------------
    if (wid == 2) {
        float ro = (lane < DD) ? tanhf(tail_boost_w[(long)rb * DD + lane]) * (1.0f / DIMV) : 0.f;
        s_ro[lane] = ro;                                  // lane 31 writes 0
        float v2 = warp_sum(ro * ro);
        if (lane == 0) {
            float zeta = 1.0f / (sqrtf(1.0f - v2) + 1e-8f);
            s_par[0] = zeta;
            s_par[1] = (zeta - 1.0f) / (v2 + 1e-9f);
        }
    } else if (wid == 3) {
#pragma unroll 1
        for (int i = 0; i < DD; i++) {
            float w  = (lane < DD) ? s_wt[i][lane] : 0.f;
            float n2 = warp_sum(w * w);
            if (lane == 0) s_beta[i] = -2.0f / n2;
        }
    } else if (wid == 4) {
#pragma unroll 1
        for (int i = 0; i < DD; i++) {
            float w  = (lane < DD) ? s_wh[i][lane] : 0.f;
            float n2 = warp_sum(w * w);
            if (lane == 0) s_wh[i][DD] = 2.0f / n2;
        }
    } else if (wid == 5) {
        if (lane == 0) s_par[2] = tanhf(bias_head[g_u[b]]);
    }
    __syncthreads();

    // ---- Build (warp 0): lane owns column `lane` of P = H31..H1 (= row `lane` of Q);
    //      fold the tail boost in as a rank-1 correction, write s_T. Plain C, regs only.
    if (wid == 0) {
        const float zt = s_par[0];
        const float kp = s_par[1];
        if (lane < DD) {
            float P[DIMV];
#pragma unroll
            for (int k = 0; k < DIMV; k++) P[k] = (k == lane) ? 1.f : 0.f;

#pragma unroll 1
            for (int i = 0; i < DD; i++) {
                float z0 = 0.f, z1 = 0.f, z2 = 0.f, z3 = 0.f;
#pragma unroll
                for (int k = 0; k < DIMV; k += 4) {
                    z0 = fmaf(s_wt[i][k],     P[k],     z0);
                    z1 = fmaf(s_wt[i][k + 1], P[k + 1], z1);
                    z2 = fmaf(s_wt[i][k + 2], P[k + 2], z2);
                    z3 = fmaf(s_wt[i][k + 3], P[k + 3], z3);
                }
                const float g = s_beta[i] * ((z0 + z1) + (z2 + z3));
#pragma unroll
                for (int k = 0; k < DIMV; k++) P[k] = fmaf(g, s_wt[i][k], P[k]);
            }
            // s = Q[lane] . ro  (in-lane, since P column = Q row)
            float s0 = 0.f, s1 = 0.f, s2 = 0.f, s3 = 0.f;
#pragma unroll
            for (int k = 0; k < DIMV; k += 4) {
                s0 = fmaf(s_ro[k],     P[k],     s0);
                s1 = fmaf(s_ro[k + 1], P[k + 1], s1);
                s2 = fmaf(s_ro[k + 2], P[k + 2], s2);
                s3 = fmaf(s_ro[k + 3], P[k + 3], s3);
            }
            const float s  = (s0 + s1) + (s2 + s3);
            const float ks = kp * s;
            float* row = &s_T[lane + 1][0];
            row[0] = -zt * s;
#pragma unroll
            for (int m = 0; m < DD; m++) row[1 + m] = fmaf(ks, s_ro[m], P[m]);
        } else {
            // lane 31: s_T row 0 = [ zeta, -zeta*ro_0 .. -zeta*ro_30 ]
            float* row = &s_T[0][0];
            row[0] = zt;
#pragma unroll
            for (int j = 0; j < DD; j++) row[1 + j] = -zt * s_ro[j];
        }
    }
    // ---------------- Head chain (warp 1, concurrent with build) ----------------
    else if (wid == 1) {
        float c = emb[(long)g_u[b] * DIMV + lane];
#pragma unroll 1
        for (int i = 0; i < DD; i++) {
            float w   = (lane >= 1) ? s_wh[i][lane - 1] : 0.f;
            float sc  = s_wh[i][DD];
            float dot = warp_sum(c * w);
            c = fmaf(-sc * dot, w, c);
        }
        float rh   = (lane >= 1) ? tanhf(head_boost_w[(long)rb * DD + lane - 1]) * (1.0f / DIMV) : 0.f;
        float v2   = warp_sum(rh * rh);
        float zeta = 1.0f / (sqrtf(1.0f - v2) + 1e-8f);
        float coef = (zeta - 1.0f) / (v2 + 1e-9f);
        float tval = __shfl_sync(0xffffffffu, c, 0);
        float dotb = warp_sum(c * rh);
        float res;
        if (lane == 0) res = zeta * tval - zeta * dotb;
        else           res = -zeta * tval * rh + c + coef * rh * dotb;
        s_th[lane] = res;
    }
    __syncthreads();

    // ---------------- Phase C: y = x^T . s_T  (y preloaded with -th), distance ------
    const float tbh = s_par[2];

    for (int n = tid; n < N; n += 256) {
        const int vi = g_v[(long)b * N + n];
        const float4* ep = (const float4*)(emb + (long)vi * DIMV);
        float4 xq[8];
#pragma unroll
        for (int q = 0; q < 8; q++) xq[q] = ep[q];
        const float btail = bias_tail[vi];

        float y[DIMV];
#pragma unroll
        for (int c = 0; c < DIMV; c++) y[c] = -s_th[c];

#pragma unroll
        for (int q = 0; q < 8; q++) {
            const float xa = xq[q].x, xb = xq[q].y, xc = xq[q].z, xd = xq[q].w;
            const float* r0 = &s_T[4 * q + 0][0];
            const float* r1 = &s_T[4 * q + 1][0];
            const float* r2 = &s_T[4 * q + 2][0];
            const float* r3 = &s_T[4 * q + 3][0];
#pragma unroll
            for (int c = 0; c < DIMV; c++) {
                float t = fmaf(xa, r0[c], y[c]);
                t = fmaf(xb, r1[c], t);
                t = fmaf(xc, r2[c], t);
                y[c] = fmaf(xd, r3[c], t);
            }
        }

        float a0 = 0.f, a1 = 0.f, a2 = 0.f, a3 = 0.f;
#pragma unroll
        for (int c = 0; c < DIMV; c += 4) {
            a0 = fmaf(y[c],     y[c],     a0);
            a1 = fmaf(y[c + 1], y[c + 1], a1);
            a2 = fmaf(y[c + 2], y[c + 2], a2);
            a3 = fmaf(y[c + 3], y[c + 3], a3);
        }
        const float acc = (a0 + a1) + (a2 + a3);
        const float mkv = acc - 2.f * y[0] * y[0];

        out[(long)b * N + n] = MARGIN - mkv + tbh + tanhf(btail);
    }
}

extern "C" void kernel_launch(void* const* d_in, const int* in_sizes, int n_in,
                              void* d_out, int out_size) {
    const int*   u   = (const int*)d_in[0];
    const int*   r   = (const int*)d_in[1];
    const int*   v   = (const int*)d_in[2];
    const float* emb = (const float*)d_in[3];
    const float* bh  = (const float*)d_in[4];
    const float* bt  = (const float*)d_in[5];
    const float* hrw = (const float*)d_in[6];
    const float* hbw = (const float*)d_in[7];
    const float* trw = (const float*)d_in[8];
    const float* tbw = (const float*)d_in[9];
    float* out = (float*)d_out;

    const int B = in_sizes[0];
    const int N = in_sizes[2] / B;

    hypernet_kernel<<<B, 256>>>(u, r, v, emb, bh, bt, hrw, hbw, trw, tbw, out, N);
}

// round 12
// speedup vs baseline: 5.0227x; 5.0227x over previous
#include <cuda_runtime.h>
#include <math.h>

#define DD 31
#define DIMV 32
#define TSTRIDE 36   // floats per s_T row (32 data + 4 pad; 144B keeps rows 16B-aligned)
#define MARGIN 0.85f

__device__ __forceinline__ float gelu_exact(float x) {
    return 0.5f * x * (1.0f + erff(x * 0.70710678118654752440f));
}

__device__ __forceinline__ float warp_sum(float v) {
#pragma unroll
    for (int o = 16; o; o >>= 1) v += __shfl_xor_sync(0xffffffffu, v, o);
    return v;
}

__global__ __launch_bounds__(128, 2)
void hypernet_kernel(const int* __restrict__ g_u, const int* __restrict__ g_r,
                     const int* __restrict__ g_v, const float* __restrict__ emb,
                     const float* __restrict__ bias_head, const float* __restrict__ bias_tail,
                     const float* __restrict__ head_rot_w, const float* __restrict__ head_boost_w,
                     const float* __restrict__ tail_rot_w, const float* __restrict__ tail_boost_w,
                     float* __restrict__ out, int N) {
    __shared__ __align__(16) float s_wt[DD][DIMV];      // gelu'd tail Householder rows; col31 = 0
    __shared__ __align__(16) float s_wh[DD][DIMV];      // gelu'd head rows; [i][31] = 2/n2
    __shared__ __align__(16) float s_T[DIMV][TSTRIDE];  // fused rot+boost matrix, row = input dim
    __shared__ __align__(16) float s_th[DIMV];          // transformed head vector (time at [0])
    __shared__ __align__(16) float s_ro[DIMV];          // tail rapidity (31 vals) + pad 0
    __shared__ float s_beta[DD];                        // -2/n2 per tail reflection
    __shared__ float s_par[4];                          // zeta_t, kappa_t, tanh(bias_head[u])

    const int b    = blockIdx.x;
    const int tid  = threadIdx.x;
    const int lane = tid & 31;
    const int wid  = tid >> 5;   // 0..3
    const int rb   = g_r[b];

    // ---------------- Phase A: gelu both rotation tables into shared ----------------
    const float* tw = tail_rot_w + (long)rb * (DD * DD);
    const float* hw = head_rot_w + (long)rb * (DD * DD);
    for (int k = tid; k < DD * DIMV; k += 128) {
        int i = k >> 5, j = k & 31;
        s_wt[i][j] = (j < DD) ? gelu_exact(tw[i * DD + j]) : 0.f;
        s_wh[i][j] = (j < DD) ? gelu_exact(hw[i * DD + j]) : 0.f;
    }
    __syncthreads();

    // ---------------- Phase A2 (4 warps): boost params / norms / head bias ----------
    if (wid == 0) {
        float ro = (lane < DD) ? tanhf(tail_boost_w[(long)rb * DD + lane]) * (1.0f / DIMV) : 0.f;
        s_ro[lane] = ro;                                  // lane 31 writes 0
        float v2 = warp_sum(ro * ro);
        if (lane == 0) {
            float zeta = 1.0f / (sqrtf(1.0f - v2) + 1e-8f);
            s_par[0] = zeta;
            s_par[1] = (zeta - 1.0f) / (v2 + 1e-9f);
        }
    } else if (wid == 1) {
#pragma unroll 1
        for (int i = 0; i < DD; i++) {
            float w  = (lane < DD) ? s_wt[i][lane] : 0.f;
            float n2 = warp_sum(w * w);
            if (lane == 0) s_beta[i] = -2.0f / n2;
        }
    } else if (wid == 2) {
#pragma unroll 1
        for (int i = 0; i < DD; i++) {
            float w  = (lane < DD) ? s_wh[i][lane] : 0.f;
            float n2 = warp_sum(w * w);
            if (lane == 0) s_wh[i][DD] = 2.0f / n2;
        }
    } else {
        if (lane == 0) s_par[2] = tanhf(bias_head[g_u[b]]);
    }
    __syncthreads();

    // ---- Build (warp 0): lane owns column `lane` of P = H31..H1 (= row `lane` of Q);
    //      fold tail boost as rank-1 correction, write s_T.
    if (wid == 0) {
        const float zt = s_par[0];
        const float kp = s_par[1];
        if (lane < DD) {
            float P[DIMV];
#pragma unroll
            for (int k = 0; k < DIMV; k++) P[k] = (k == lane) ? 1.f : 0.f;

#pragma unroll 1
            for (int i = 0; i < DD; i++) {
                float z0 = 0.f, z1 = 0.f, z2 = 0.f, z3 = 0.f;
#pragma unroll
                for (int k = 0; k < DIMV; k += 4) {
                    z0 = fmaf(s_wt[i][k],     P[k],     z0);
                    z1 = fmaf(s_wt[i][k + 1], P[k + 1], z1);
                    z2 = fmaf(s_wt[i][k + 2], P[k + 2], z2);
                    z3 = fmaf(s_wt[i][k + 3], P[k + 3], z3);
                }
                const float g = s_beta[i] * ((z0 + z1) + (z2 + z3));
#pragma unroll
                for (int k = 0; k < DIMV; k++) P[k] = fmaf(g, s_wt[i][k], P[k]);
            }
            float s0 = 0.f, s1 = 0.f, s2 = 0.f, s3 = 0.f;
#pragma unroll
            for (int k = 0; k < DIMV; k += 4) {
                s0 = fmaf(s_ro[k],     P[k],     s0);
                s1 = fmaf(s_ro[k + 1], P[k + 1], s1);
                s2 = fmaf(s_ro[k + 2], P[k + 2], s2);
                s3 = fmaf(s_ro[k + 3], P[k + 3], s3);
            }
            const float s  = (s0 + s1) + (s2 + s3);
            const float ks = kp * s;
            float* row = &s_T[lane + 1][0];
            row[0] = -zt * s;
#pragma unroll
            for (int m = 0; m < DD; m++) row[1 + m] = fmaf(ks, s_ro[m], P[m]);
        } else {
            float* row = &s_T[0][0];
            row[0] = zt;
#pragma unroll
            for (int j = 0; j < DD; j++) row[1 + j] = -zt * s_ro[j];
        }
    }
    // ---------------- Head chain (warp 1, concurrent with build) ----------------
    else if (wid == 1) {
        float c = emb[(long)g_u[b] * DIMV + lane];
#pragma unroll 1
        for (int i = 0; i < DD; i++) {
            float w   = (lane >= 1) ? s_wh[i][lane - 1] : 0.f;
            float sc  = s_wh[i][DD];
            float dot = warp_sum(c * w);
            c = fmaf(-sc * dot, w, c);
        }
        float rh   = (lane >= 1) ? tanhf(head_boost_w[(long)rb * DD + lane - 1]) * (1.0f / DIMV) : 0.f;
        float v2   = warp_sum(rh * rh);
        float zeta = 1.0f / (sqrtf(1.0f - v2) + 1e-8f);
        float coef = (zeta - 1.0f) / (v2 + 1e-9f);
        float tval = __shfl_sync(0xffffffffu, c, 0);
        float dotb = warp_sum(c * rh);
        float res;
        if (lane == 0) res = zeta * tval - zeta * dotb;
        else           res = -zeta * tval * rh + c + coef * rh * dotb;
        s_th[lane] = res;
    }
    __syncthreads();

    // ------- Phase C: TWO vectors per thread share one streamed pass over s_T -------
    const float tbh = s_par[2];

    for (int base = 0; base < N; base += 256) {
        const int na = base + tid;
        if (na >= N) break;
        const int nb = na + 128;
        const bool has_b = (nb < N);

        const int via = g_v[(long)b * N + na];
        const int vib = has_b ? g_v[(long)b * N + nb] : via;

        const float4* ea = (const float4*)(emb + (long)via * DIMV);
        const float4* eb = (const float4*)(emb + (long)vib * DIMV);
        const float bta = bias_tail[via];
        const float btb = has_b ? bias_tail[vib] : 0.f;

        float ya[DIMV], yb[DIMV];
#pragma unroll
        for (int c = 0; c < DIMV; c++) { float t = -s_th[c]; ya[c] = t; yb[c] = t; }

#pragma unroll
        for (int q = 0; q < 8; q++) {
            const float4 xa4 = ea[q];
            const float4 xb4 = eb[q];
#pragma unroll
            for (int r = 0; r < 4; r++) {
                const float xa = (r == 0) ? xa4.x : (r == 1) ? xa4.y : (r == 2) ? xa4.z : xa4.w;
                const float xb = (r == 0) ? xb4.x : (r == 1) ? xb4.y : (r == 2) ? xb4.z : xb4.w;
                const float* row = &s_T[4 * q + r][0];
#pragma unroll
                for (int c = 0; c < DIMV; c++) {
                    const float tc = row[c];
                    ya[c] = fmaf(xa, tc, ya[c]);
                    yb[c] = fmaf(xb, tc, yb[c]);
                }
            }
        }

        float a0 = 0.f, a1 = 0.f, a2 = 0.f, a3 = 0.f;
        float b0 = 0.f, b1 = 0.f, b2 = 0.f, b3 = 0.f;
#pragma unroll
        for (int c = 0; c < DIMV; c += 4) {
            a0 = fmaf(ya[c],     ya[c],     a0);
            a1 = fmaf(ya[c + 1], ya[c + 1], a1);
            a2 = fmaf(ya[c + 2], ya[c + 2], a2);
            a3 = fmaf(ya[c + 3], ya[c + 3], a3);
            b0 = fmaf(yb[c],     yb[c],     b0);
            b1 = fmaf(yb[c + 1], yb[c + 1], b1);
            b2 = fmaf(yb[c + 2], yb[c + 2], b2);
            b3 = fmaf(yb[c + 3], yb[c + 3], b3);
        }
        const float acca = (a0 + a1) + (a2 + a3);
        const float accb = (b0 + b1) + (b2 + b3);
        const float mkva = acca - 2.f * ya[0] * ya[0];
        const float mkvb = accb - 2.f * yb[0] * yb[0];

        out[(long)b * N + na] = MARGIN - mkva + tbh + tanhf(bta);
        if (has_b)
            out[(long)b * N + nb] = MARGIN - mkvb + tbh + tanhf(btb);
    }
}

extern "C" void kernel_launch(void* const* d_in, const int* in_sizes, int n_in,
                              void* d_out, int out_size) {
    const int*   u   = (const int*)d_in[0];
    const int*   r   = (const int*)d_in[1];
    const int*   v   = (const int*)d_in[2];
    const float* emb = (const float*)d_in[3];
    const float* bh  = (const float*)d_in[4];
    const float* bt  = (const float*)d_in[5];
    const float* hrw = (const float*)d_in[6];
    const float* hbw = (const float*)d_in[7];
    const float* trw = (const float*)d_in[8];
    const float* tbw = (const float*)d_in[9];
    float* out = (float*)d_out;

    const int B = in_sizes[0];
    const int N = in_sizes[2] / B;

    hypernet_kernel<<<B, 128>>>(u, r, v, emb, bh, bt, hrw, hbw, trw, tbw, out, N);
}